// round 1
// baseline (speedup 1.0000x reference)
#include <cuda_runtime.h>
#include <cstdint>
#include <cstddef>

// Problem constants
#define B_  32
#define T_  512
#define E_  300
#define H_  1024
#define G4_ 4096            // 4*H
#define M_  (B_*T_)         // 16384 token rows
#define NCTA_REC 128

// ---------------- scratch (device globals; no allocation allowed) ----------
__device__ float g_x   [(size_t)M_ * E_];        // embedded inputs
__device__ float g_xpF [(size_t)M_ * G4_];       // input projection, fwd dir
__device__ float g_xpB [(size_t)M_ * G4_];       // input projection, bwd dir
__device__ float g_out0[(size_t)M_ * 2 * H_];    // layer0 output [out_f || out_b]
__device__ float g_hF  [B_ * H_];
__device__ float g_hB  [B_ * H_];
__device__ unsigned g_bar_count;                 // zero-initialized
__device__ volatile unsigned g_bar_gen;          // zero-initialized

// ---------------- helpers ---------------------------------------------------
__device__ __forceinline__ uint32_t f2tf(float f) {
    uint32_t u;
    asm("cvt.rna.tf32.f32 %0, %1;" : "=r"(u) : "f"(f));
    return u;
}

__device__ __forceinline__ void mma8(float* c, const uint32_t* a, const uint32_t* b) {
    asm volatile(
        "mma.sync.aligned.m16n8k8.row.col.f32.tf32.tf32.f32 "
        "{%0,%1,%2,%3},{%4,%5,%6,%7},{%8,%9},{%0,%1,%2,%3};"
        : "+f"(c[0]), "+f"(c[1]), "+f"(c[2]), "+f"(c[3])
        : "r"(a[0]), "r"(a[1]), "r"(a[2]), "r"(a[3]), "r"(b[0]), "r"(b[1]));
}

__device__ __forceinline__ float sigmoidf_(float x) { return 1.f / (1.f + __expf(-x)); }

// Software grid barrier. Grid is exactly NCTA_REC CTAs, one per SM (single
// wave guaranteed), so spinning is safe.
__device__ __forceinline__ void grid_barrier() {
    __threadfence();
    __syncthreads();
    if (threadIdx.x == 0) {
        unsigned g = g_bar_gen;
        if (atomicAdd(&g_bar_count, 1u) == (unsigned)(NCTA_REC - 1)) {
            atomicExch(&g_bar_count, 0u);
            __threadfence();
            g_bar_gen = g + 1u;
        } else {
            while (g_bar_gen == g) { }
        }
    }
    __syncthreads();
}

// ---------------- kernel 1: embedding gather -------------------------------
__global__ __launch_bounds__(256) void gather_kernel(
    const int* __restrict__ tok, const float* __restrict__ emb, float* __restrict__ x)
{
    int i = blockIdx.x * 256 + threadIdx.x;
    if (i >= M_ * E_) return;
    int bt = i / E_;
    int e  = i - bt * E_;
    x[i] = emb[(size_t)tok[bt] * E_ + e];
}

// ---------------- kernel 2: tf32 GEMM  C = A * Bw^T + bias1 + bias2 --------
// A: M x K row-major, Bw: N x K row-major, C: M x N row-major.
// Tiles: 128x128x16, 8 warps (4m x 2n), warp tile 32x64.
__global__ __launch_bounds__(256) void gemm_tf32(
    const float* __restrict__ A, const float* __restrict__ Bw,
    const float* __restrict__ bias1, const float* __restrict__ bias2,
    float* __restrict__ C, int M, int N, int K)
{
    __shared__ uint32_t As[2][128][20];   // pad 20 -> conflict-free frag loads
    __shared__ uint32_t Bs[2][128][20];

    const int tid  = threadIdx.x;
    const int warp = tid >> 5, lane = tid & 31;
    const int m0 = blockIdx.y * 128, n0 = blockIdx.x * 128;
    const int wm = (warp >> 1) * 32, wn = (warp & 1) * 64;

    float acc[2][8][4];
#pragma unroll
    for (int i = 0; i < 2; i++)
#pragma unroll
        for (int j = 0; j < 8; j++)
#pragma unroll
            for (int k = 0; k < 4; k++) acc[i][j][k] = 0.f;

    float rA[8], rB[8];
    const int nc = (K + 15) / 16;

    auto ldg = [&](int kc) {
#pragma unroll
        for (int i = 0; i < 8; i++) {
            int e = tid + i * 256;
            int r = e >> 4;
            int kk = kc + (e & 15);
            rA[i] = (kk < K) ? A [(size_t)(m0 + r) * K + kk] : 0.f;
            rB[i] = (kk < K) ? Bw[(size_t)(n0 + r) * K + kk] : 0.f;
        }
    };
    auto sts = [&](int buf) {
#pragma unroll
        for (int i = 0; i < 8; i++) {
            int e = tid + i * 256;
            int r = e >> 4, kk = e & 15;
            As[buf][r][kk] = f2tf(rA[i]);
            Bs[buf][r][kk] = f2tf(rB[i]);
        }
    };

    ldg(0); sts(0); __syncthreads();
    for (int c = 0; c < nc; c++) {
        const int buf = c & 1;
        if (c + 1 < nc) ldg((c + 1) * 16);
#pragma unroll
        for (int kk = 0; kk < 16; kk += 8) {
            uint32_t af[2][4], bf[8][2];
            const int kq = kk + (lane & 3);
#pragma unroll
            for (int mt = 0; mt < 2; mt++) {
                int r = wm + mt * 16 + (lane >> 2);
                af[mt][0] = As[buf][r][kq];
                af[mt][1] = As[buf][r + 8][kq];
                af[mt][2] = As[buf][r][kq + 4];
                af[mt][3] = As[buf][r + 8][kq + 4];
            }
#pragma unroll
            for (int nt = 0; nt < 8; nt++) {
                int r = wn + nt * 8 + (lane >> 2);
                bf[nt][0] = Bs[buf][r][kq];
                bf[nt][1] = Bs[buf][r][kq + 4];
            }
#pragma unroll
            for (int mt = 0; mt < 2; mt++)
#pragma unroll
                for (int nt = 0; nt < 8; nt++)
                    mma8(acc[mt][nt], af[mt], bf[nt]);
        }
        __syncthreads();
        if (c + 1 < nc) { sts((c + 1) & 1); __syncthreads(); }
    }

#pragma unroll
    for (int mt = 0; mt < 2; mt++)
#pragma unroll
        for (int nt = 0; nt < 8; nt++) {
            int row = m0 + wm + mt * 16 + (lane >> 2);
            int col = n0 + wn + nt * 8 + 2 * (lane & 3);
            float bv0 = bias1[col] + bias2[col];
            float bv1 = bias1[col + 1] + bias2[col + 1];
            C[(size_t)row * N + col]         = acc[mt][nt][0] + bv0;
            C[(size_t)row * N + col + 1]     = acc[mt][nt][1] + bv1;
            C[(size_t)(row + 8) * N + col]     = acc[mt][nt][2] + bv0;
            C[(size_t)(row + 8) * N + col + 1] = acc[mt][nt][3] + bv1;
        }
}

// ---------------- kernel 3: persistent bi-LSTM layer -----------------------
// 128 CTAs: [0,64) forward, [64,128) backward. Each CTA owns 16 hidden
// columns j in [j0, j0+16): gate rows {g*1024 + j0 + jl} for g=0..3 (i,f,g,o).
// Per step: gates(32x64) = h(32x1024) @ Wsel(64x1024)^T via tf32 mma,
// then the LSTM cell with SMEM-resident c/h state, then a grid barrier.
__global__ __launch_bounds__(256) void lstm_layer_kernel(
    const float* __restrict__ xpF, const float* __restrict__ xpB,
    const float* __restrict__ WhF, const float* __restrict__ WhB,
    const int* __restrict__ lengths,
    float* __restrict__ out,                 // (B*T) x 2H or nullptr
    float* __restrict__ hF, float* __restrict__ hB)
{
    __shared__ uint32_t Hs[32][68];          // h chunk (tf32), pad 68
    __shared__ uint32_t Ws[64][68];          // W chunk (tf32)
    __shared__ float    Gs[32][64];          // gate tile
    __shared__ float    cst[32][16];         // cell state (this CTA's slice)
    __shared__ float    hst[32][16];         // hidden state (this CTA's slice)

    const int tid  = threadIdx.x;
    const int warp = tid >> 5, lane = tid & 31;
    const int cta  = blockIdx.x;
    const int dir  = (cta >= 64) ? 1 : 0;
    const int j0   = (cta & 63) * 16;
    const float* xp   = dir ? xpB : xpF;
    const float* Wh   = dir ? WhB : WhF;
    float*       hdir = dir ? hB : hF;

    // init h = c = 0
    for (int p = tid; p < 512; p += 256) {
        int b = p >> 4, jl = p & 15;
        cst[b][jl] = 0.f;
        hst[b][jl] = 0.f;
        hdir[b * H_ + j0 + jl] = 0.f;
    }
    grid_barrier();

    for (int t = 0; t < T_; t++) {
        float acc[2][4];
#pragma unroll
        for (int mt = 0; mt < 2; mt++)
#pragma unroll
            for (int k = 0; k < 4; k++) acc[mt][k] = 0.f;

        float rH[8], rW[16];
        auto ldchunk = [&](int kc) {
#pragma unroll
            for (int i = 0; i < 8; i++) {
                int e = tid + i * 256;
                int b = e >> 6, k = e & 63;
                rH[i] = __ldcg(&hdir[b * H_ + kc + k]);   // L2-coherent read of h
            }
#pragma unroll
            for (int i = 0; i < 16; i++) {
                int e = tid + i * 256;
                int lr = e >> 6, k = e & 63;
                int gr = (lr >> 4) * H_ + j0 + (lr & 15);
                rW[i] = Wh[(size_t)gr * H_ + kc + k];
            }
        };
        auto stchunk = [&]() {
#pragma unroll
            for (int i = 0; i < 8; i++) {
                int e = tid + i * 256;
                Hs[e >> 6][e & 63] = f2tf(rH[i]);
            }
#pragma unroll
            for (int i = 0; i < 16; i++) {
                int e = tid + i * 256;
                Ws[e >> 6][e & 63] = f2tf(rW[i]);
            }
        };

        ldchunk(0);
        for (int c = 0; c < 16; c++) {
            stchunk();
            __syncthreads();
            if (c < 15) ldchunk((c + 1) * 64);
#pragma unroll
            for (int kk = 0; kk < 64; kk += 8) {
                const int kq = kk + (lane & 3);
                uint32_t bf[2];
                bf[0] = Ws[warp * 8 + (lane >> 2)][kq];
                bf[1] = Ws[warp * 8 + (lane >> 2)][kq + 4];
#pragma unroll
                for (int mt = 0; mt < 2; mt++) {
                    int r = mt * 16 + (lane >> 2);
                    uint32_t af[4];
                    af[0] = Hs[r][kq];
                    af[1] = Hs[r + 8][kq];
                    af[2] = Hs[r][kq + 4];
                    af[3] = Hs[r + 8][kq + 4];
                    mma8(acc[mt], af, bf);
                }
            }
            __syncthreads();
        }

        // dump gate fragments to SMEM
        {
            int rowb = lane >> 2;
            int colb = warp * 8 + 2 * (lane & 3);
#pragma unroll
            for (int mt = 0; mt < 2; mt++) {
                Gs[mt * 16 + rowb][colb]         = acc[mt][0];
                Gs[mt * 16 + rowb][colb + 1]     = acc[mt][1];
                Gs[mt * 16 + rowb + 8][colb]     = acc[mt][2];
                Gs[mt * 16 + rowb + 8][colb + 1] = acc[mt][3];
            }
        }
        __syncthreads();

        // LSTM cell elementwise (512 (b, jl) pairs)
        for (int p = tid; p < 512; p += 256) {
            int b  = p >> 4, jl = p & 15;
            int len = lengths[b];
            bool msk = (t < len);
            int teff, pout;
            if (!dir) { teff = t; pout = t; }
            else {
                teff = (t < len) ? (len - 1 - t) : 0;
                pout = (t < len) ? (len - 1 - t) : t;
            }
            size_t xbase = ((size_t)(b * T_ + teff)) * G4_ + j0 + jl;
            float gi = Gs[b][jl]        + xp[xbase];
            float gf = Gs[b][16 + jl]   + xp[xbase + H_];
            float gg = Gs[b][32 + jl]   + xp[xbase + 2 * H_];
            float go = Gs[b][48 + jl]   + xp[xbase + 3 * H_];
            if (msk) {
                float ii = sigmoidf_(gi), ff = sigmoidf_(gf);
                float gv = tanhf(gg),     oo = sigmoidf_(go);
                float cn = ff * cst[b][jl] + ii * gv;
                float hn = oo * tanhf(cn);
                cst[b][jl] = cn;
                hst[b][jl] = hn;
                hdir[b * H_ + j0 + jl] = hn;
            }
            if (out) {
                out[((size_t)(b * T_ + pout)) * (2 * H_) + dir * H_ + j0 + jl] = hst[b][jl];
            }
        }
        grid_barrier();
    }
}

// ---------------- kernel 4: final linear  out = [h2b, h2f] @ lin_w^T + b ---
__global__ __launch_bounds__(256) void final_linear_kernel(
    const float* __restrict__ hF, const float* __restrict__ hB,
    const float* __restrict__ lw, const float* __restrict__ lb,
    float* __restrict__ outp)
{
    int w = (blockIdx.x * blockDim.x + threadIdx.x) >> 5;
    int lane = threadIdx.x & 31;
    if (w >= B_ * 2) return;
    int b = w >> 1, c = w & 1;
    float s = 0.f;
    for (int k = lane; k < 2 * H_; k += 32) {
        float xv = (k < H_) ? hB[b * H_ + k] : hF[b * H_ + (k - H_)];
        s += xv * lw[c * 2 * H_ + k];
    }
#pragma unroll
    for (int o = 16; o; o >>= 1) s += __shfl_xor_sync(0xffffffffu, s, o);
    if (lane == 0) outp[b * 2 + c] = s + lb[c];
}

// ---------------- launch ----------------------------------------------------
extern "C" void kernel_launch(void* const* d_in, const int* in_sizes, int n_in,
                              void* d_out, int out_size)
{
    const int*   tok      = (const int*)  d_in[0];
    const int*   lens     = (const int*)  d_in[1];
    const float* emb      = (const float*)d_in[2];
    const float* w_ih_l0f = (const float*)d_in[3];
    const float* w_hh_l0f = (const float*)d_in[4];
    const float* b_ih_l0f = (const float*)d_in[5];
    const float* b_hh_l0f = (const float*)d_in[6];
    const float* w_ih_l0b = (const float*)d_in[7];
    const float* w_hh_l0b = (const float*)d_in[8];
    const float* b_ih_l0b = (const float*)d_in[9];
    const float* b_hh_l0b = (const float*)d_in[10];
    const float* w_ih_l1f = (const float*)d_in[11];
    const float* w_hh_l1f = (const float*)d_in[12];
    const float* b_ih_l1f = (const float*)d_in[13];
    const float* b_hh_l1f = (const float*)d_in[14];
    const float* w_ih_l1b = (const float*)d_in[15];
    const float* w_hh_l1b = (const float*)d_in[16];
    const float* b_ih_l1b = (const float*)d_in[17];
    const float* b_hh_l1b = (const float*)d_in[18];
    const float* lin_w    = (const float*)d_in[19];
    const float* lin_b    = (const float*)d_in[20];

    float *x, *xpF, *xpB, *out0, *hF, *hB;
    cudaGetSymbolAddress((void**)&x,    g_x);
    cudaGetSymbolAddress((void**)&xpF,  g_xpF);
    cudaGetSymbolAddress((void**)&xpB,  g_xpB);
    cudaGetSymbolAddress((void**)&out0, g_out0);
    cudaGetSymbolAddress((void**)&hF,   g_hF);
    cudaGetSymbolAddress((void**)&hB,   g_hB);

    // 1. embedding gather
    gather_kernel<<<(M_ * E_ + 255) / 256, 256>>>(tok, emb, x);

    // 2. layer-0 input projections (K = 300)
    dim3 gg(G4_ / 128, M_ / 128);
    gemm_tf32<<<gg, 256>>>(x, w_ih_l0f, b_ih_l0f, b_hh_l0f, xpF, M_, G4_, E_);
    gemm_tf32<<<gg, 256>>>(x, w_ih_l0b, b_ih_l0b, b_hh_l0b, xpB, M_, G4_, E_);

    // 3. layer-0 recurrence (writes [out_f || out_b])
    lstm_layer_kernel<<<NCTA_REC, 256>>>(xpF, xpB, w_hh_l0f, w_hh_l0b, lens,
                                         out0, hF, hB);

    // 4. layer-1 input projections (K = 2048)
    gemm_tf32<<<gg, 256>>>(out0, w_ih_l1f, b_ih_l1f, b_hh_l1f, xpF, M_, G4_, 2 * H_);
    gemm_tf32<<<gg, 256>>>(out0, w_ih_l1b, b_ih_l1b, b_hh_l1b, xpB, M_, G4_, 2 * H_);

    // 5. layer-1 recurrence (only final hiddens needed)
    lstm_layer_kernel<<<NCTA_REC, 256>>>(xpF, xpB, w_hh_l1f, w_hh_l1b, lens,
                                         (float*)nullptr, hF, hB);

    // 6. head: out = [h2b, h2f] @ lin_w^T + lin_b
    final_linear_kernel<<<8, 256>>>(hF, hB, lin_w, lin_b, (float*)d_out);
}

// round 2
// speedup vs baseline: 1.4013x; 1.4013x over previous
#include <cuda_runtime.h>
#include <cstdint>
#include <cstddef>

// Problem constants
#define B_   32
#define T_   512
#define E_   300
#define EP_  320              // padded embedding K (mult of 32)
#define H_   1024
#define G4_  4096             // 4*H
#define M_   (B_*T_)          // 16384 token rows
#define NCTA_REC 128

// ---------------- scratch (device globals; no allocation allowed) ----------
__device__ uint32_t g_x   [(size_t)M_ * EP_];      // embedded inputs (tf32)
__device__ uint32_t g_wA  [(size_t)G4_ * 2048];    // converted w_ih (dir f)
__device__ uint32_t g_wB  [(size_t)G4_ * 2048];    // converted w_ih (dir b)
__device__ uint32_t g_whF [(size_t)G4_ * H_];      // converted w_hh fwd
__device__ uint32_t g_whB [(size_t)G4_ * H_];      // converted w_hh bwd
__device__ float    g_xpF [(size_t)M_ * G4_];      // input projection fwd
__device__ float    g_xpB [(size_t)M_ * G4_];      // input projection bwd
__device__ uint32_t g_out0[(size_t)M_ * 2 * H_];   // layer0 output (tf32)
__device__ uint32_t g_hF  [B_ * H_];
__device__ uint32_t g_hB  [B_ * H_];
__device__ unsigned g_bar_count;
__device__ volatile unsigned g_bar_gen;

// ---------------- helpers ---------------------------------------------------
__device__ __forceinline__ uint32_t f2tf(float f) {
    uint32_t u;
    asm("cvt.rna.tf32.f32 %0, %1;" : "=r"(u) : "f"(f));
    return u;
}

__device__ __forceinline__ void mma8(float* c, const uint32_t* a, const uint32_t* b) {
    asm volatile(
        "mma.sync.aligned.m16n8k8.row.col.f32.tf32.tf32.f32 "
        "{%0,%1,%2,%3},{%4,%5,%6,%7},{%8,%9},{%0,%1,%2,%3};"
        : "+f"(c[0]), "+f"(c[1]), "+f"(c[2]), "+f"(c[3])
        : "r"(a[0]), "r"(a[1]), "r"(a[2]), "r"(a[3]), "r"(b[0]), "r"(b[1]));
}

__device__ __forceinline__ float sigmoidf_(float x) { return 1.f / (1.f + __expf(-x)); }

__device__ __forceinline__ uint32_t s2u(const void* p) {
    uint32_t r;
    asm("{ .reg .u64 t; cvta.to.shared.u64 t, %1; cvt.u32.u64 %0, t; }" : "=r"(r) : "l"(p));
    return r;
}
__device__ __forceinline__ void cp16(void* smem, const void* gmem) {
    asm volatile("cp.async.cg.shared.global [%0], [%1], 16;\n" :: "r"(s2u(smem)), "l"(gmem));
}
__device__ __forceinline__ void cp_commit() { asm volatile("cp.async.commit_group;"); }
template<int N> __device__ __forceinline__ void cp_wait() {
    asm volatile("cp.async.wait_group %0;" :: "n"(N));
}

// Software grid barrier; grid is exactly NCTA_REC co-resident CTAs.
__device__ __forceinline__ void grid_barrier() {
    __threadfence();
    __syncthreads();
    if (threadIdx.x == 0) {
        unsigned g = g_bar_gen;
        if (atomicAdd(&g_bar_count, 1u) == (unsigned)(NCTA_REC - 1)) {
            atomicExch(&g_bar_count, 0u);
            __threadfence();
            g_bar_gen = g + 1u;
        } else {
            while (g_bar_gen == g) { }
        }
    }
    __syncthreads();
}

// ---------------- kernel 1: embedding gather (emit tf32, pad to 320) -------
__global__ __launch_bounds__(256) void gather_kernel(
    const int* __restrict__ tok, const float* __restrict__ emb, uint32_t* __restrict__ x)
{
    int i = blockIdx.x * 256 + threadIdx.x;
    if (i >= M_ * EP_) return;
    int bt = i / EP_;
    int e  = i - bt * EP_;
    x[i] = (e < E_) ? f2tf(emb[(size_t)tok[bt] * E_ + e]) : 0u;
}

// ---------------- kernel 1b: fp32 -> tf32 convert (with K padding) ---------
__global__ __launch_bounds__(256) void conv_tf32(
    const float* __restrict__ src, uint32_t* __restrict__ dst, int N, int K, int Kp)
{
    int i = blockIdx.x * 256 + threadIdx.x;
    if (i >= N * Kp) return;
    int n = i / Kp, k = i - n * Kp;
    dst[i] = (k < K) ? f2tf(src[(size_t)n * K + k]) : 0u;
}

// ---------------- kernel 2: tf32 GEMM, cp.async 3-stage, BK=32 -------------
// A: M x Ka row-major tf32, Bw: N x Ka row-major tf32, C: M x 4096 fp32.
// Tiles 128x128x32, 8 warps (4m x 2n), warp tile 32x64.
#define GST 3
#define GEMM_SMEM (2 * GST * 128 * 36 * 4)
__global__ __launch_bounds__(256, 2) void gemm_tf32(
    const uint32_t* __restrict__ A, const uint32_t* __restrict__ Bw,
    const float* __restrict__ bias1, const float* __restrict__ bias2,
    float* __restrict__ C, int Ka)
{
    extern __shared__ char smraw[];
    uint32_t* As = (uint32_t*)smraw;              // GST * 128 * 36
    uint32_t* Bs = As + GST * 128 * 36;

    const int tid = threadIdx.x, warp = tid >> 5, lane = tid & 31;
    const int m0 = blockIdx.y * 128, n0 = blockIdx.x * 128;
    const int wm = (warp >> 1) * 32, wn = (warp & 1) * 64;
    const uint32_t* Ag = A + (size_t)m0 * Ka;
    const uint32_t* Bg = Bw + (size_t)n0 * Ka;

    float acc[2][8][4];
#pragma unroll
    for (int i = 0; i < 2; i++)
#pragma unroll
        for (int j = 0; j < 8; j++)
#pragma unroll
            for (int k = 0; k < 4; k++) acc[i][j][k] = 0.f;

    auto issue = [&](int st, int kc) {
#pragma unroll
        for (int i = 0; i < 4; i++) {
            int seg = tid + i * 256;             // 1024 segs
            int row = seg >> 3, c4 = (seg & 7) * 4;
            cp16(As + st * 128 * 36 + row * 36 + c4, Ag + (size_t)row * Ka + kc + c4);
            cp16(Bs + st * 128 * 36 + row * 36 + c4, Bg + (size_t)row * Ka + kc + c4);
        }
    };

    const int nc = Ka >> 5;
    issue(0, 0);  cp_commit();
    issue(1, 32); cp_commit();

    for (int c = 0; c < nc; c++) {
        if (c + 1 < nc) cp_wait<1>(); else cp_wait<0>();
        __syncthreads();
        if (c + 2 < nc) { issue((c + 2) % GST, (c + 2) * 32); cp_commit(); }

        const uint32_t* ab = As + (c % GST) * 128 * 36;
        const uint32_t* bb = Bs + (c % GST) * 128 * 36;
#pragma unroll
        for (int kk = 0; kk < 32; kk += 8) {
            int kq = kk + (lane & 3);
            uint32_t af[2][4], bf[8][2];
#pragma unroll
            for (int mt = 0; mt < 2; mt++) {
                int r = wm + mt * 16 + (lane >> 2);
                af[mt][0] = ab[r * 36 + kq];
                af[mt][1] = ab[(r + 8) * 36 + kq];
                af[mt][2] = ab[r * 36 + kq + 4];
                af[mt][3] = ab[(r + 8) * 36 + kq + 4];
            }
#pragma unroll
            for (int nt = 0; nt < 8; nt++) {
                int r = wn + nt * 8 + (lane >> 2);
                bf[nt][0] = bb[r * 36 + kq];
                bf[nt][1] = bb[r * 36 + kq + 4];
            }
#pragma unroll
            for (int mt = 0; mt < 2; mt++)
#pragma unroll
                for (int nt = 0; nt < 8; nt++)
                    mma8(acc[mt][nt], af[mt], bf[nt]);
        }
    }

#pragma unroll
    for (int mt = 0; mt < 2; mt++)
#pragma unroll
        for (int nt = 0; nt < 8; nt++) {
            int row = m0 + wm + mt * 16 + (lane >> 2);
            int col = n0 + wn + nt * 8 + 2 * (lane & 3);
            float bv0 = bias1[col] + bias2[col];
            float bv1 = bias1[col + 1] + bias2[col + 1];
            C[(size_t)row * G4_ + col]           = acc[mt][nt][0] + bv0;
            C[(size_t)row * G4_ + col + 1]       = acc[mt][nt][1] + bv1;
            C[(size_t)(row + 8) * G4_ + col]     = acc[mt][nt][2] + bv0;
            C[(size_t)(row + 8) * G4_ + col + 1] = acc[mt][nt][3] + bv1;
        }
}

// ---------------- kernel 3: persistent bi-LSTM layer -----------------------
// 128 CTAs: [0,64) fwd, [64,128) bwd. Each CTA owns 16 hidden cols (64 gate
// rows). First KPC*64 columns of its W_hh slice stay resident in SMEM; the
// rest + the h vector stream via double-buffered cp.async every step.
#define KPC   9               // persistent k-chunks (of 16)
#define WPSTR 580
#define LSTM_SMEM ((64*WPSTR + 2*32*68 + 2*64*68) * 4 + 32*64*4 + 512*4 + 512*4 + 32*4)
__global__ __launch_bounds__(256) void lstm_layer_kernel(
    const float* __restrict__ xpF, const float* __restrict__ xpB,
    const uint32_t* __restrict__ WhF, const uint32_t* __restrict__ WhB,
    const int* __restrict__ lengths,
    uint32_t* __restrict__ out,           // (B*T) x 2H tf32, or nullptr
    uint32_t* __restrict__ hF, uint32_t* __restrict__ hB)
{
    extern __shared__ char smraw[];
    uint32_t* WP  = (uint32_t*)smraw;          // [64][580] persistent W
    uint32_t* HS  = WP + 64 * WPSTR;           // [2][32][68] h chunks
    uint32_t* WS  = HS + 2 * 32 * 68;          // [2][64][68] streamed W
    float*    GS  = (float*)(WS + 2 * 64 * 68);// [32][64] gates
    float*    CST = GS + 32 * 64;              // [512]
    float*    HST = CST + 512;                 // [512]
    int*      SLEN = (int*)(HST + 512);        // [32]

    const int tid = threadIdx.x, warp = tid >> 5, lane = tid & 31;
    const int cta = blockIdx.x;
    const int dir = cta >> 6;
    const int j0  = (cta & 63) * 16;
    const float*    xp   = dir ? xpB : xpF;
    const uint32_t* Wh   = dir ? WhB : WhF;
    uint32_t*       hdir = dir ? hB : hF;

    // init state + load persistent W + lengths
    for (int p = tid; p < 512; p += 256) {
        int b = p >> 4, jl = p & 15;
        CST[p] = 0.f; HST[p] = 0.f;
        hdir[b * H_ + j0 + jl] = 0u;
    }
    if (tid < 32) SLEN[tid] = lengths[tid];
    for (int i = tid; i < 64 * (KPC * 64); i += 256) {
        int r = i / (KPC * 64), k = i - r * (KPC * 64);
        WP[r * WPSTR + k] = Wh[((size_t)((r >> 4) * H_ + j0 + (r & 15))) * H_ + k];
    }
    grid_barrier();

    auto issueH = [&](int c) {
        uint32_t* dst = HS + (c & 1) * 32 * 68;
        const uint32_t* src = hdir + c * 64;
#pragma unroll
        for (int i = 0; i < 2; i++) {
            int seg = tid + i * 256;            // 512 segs of 16B
            int row = seg >> 4, c4 = (seg & 15) * 4;
            cp16(dst + row * 68 + c4, src + row * H_ + c4);
        }
    };
    auto issueW = [&](int c) {
        uint32_t* dst = WS + (c & 1) * 64 * 68;
#pragma unroll
        for (int i = 0; i < 4; i++) {
            int seg = tid + i * 256;            // 1024 segs
            int row = seg >> 4, c4 = (seg & 15) * 4;
            cp16(dst + row * 68 + c4,
                 Wh + ((size_t)((row >> 4) * H_ + j0 + (row & 15))) * H_ + c * 64 + c4);
        }
    };

    for (int t = 0; t < T_; t++) {
        // prefetch this step's xp gate inputs into registers (hides DRAM lat)
        float xr[2][4];
#pragma unroll
        for (int p2 = 0; p2 < 2; p2++) {
            int p = tid + p2 * 256, b = p >> 4, jl = p & 15;
            int len = SLEN[b];
            int teff = dir ? ((t < len) ? (len - 1 - t) : 0) : t;
            const float* xb = xp + ((size_t)(b * T_ + teff)) * G4_ + j0 + jl;
            xr[p2][0] = __ldcs(xb);
            xr[p2][1] = __ldcs(xb + H_);
            xr[p2][2] = __ldcs(xb + 2 * H_);
            xr[p2][3] = __ldcs(xb + 3 * H_);
        }

        issueH(0); cp_commit();
        issueH(1); if (1 >= KPC) issueW(1); cp_commit();

        float acc[2][4];
#pragma unroll
        for (int mt = 0; mt < 2; mt++)
#pragma unroll
            for (int k = 0; k < 4; k++) acc[mt][k] = 0.f;

        for (int c = 0; c < 16; c++) {
            if (c < 15) cp_wait<1>(); else cp_wait<0>();
            __syncthreads();

            const uint32_t* hb = HS + (c & 1) * 32 * 68;
            const uint32_t* wb; int wstr;
            if (c < KPC) { wb = WP + c * 64;           wstr = WPSTR; }
            else         { wb = WS + (c & 1) * 64 * 68; wstr = 68; }
            const uint32_t* wrow = wb + (warp * 8 + (lane >> 2)) * wstr;
#pragma unroll
            for (int kk = 0; kk < 64; kk += 8) {
                int kq = kk + (lane & 3);
                uint32_t bf[2] = { wrow[kq], wrow[kq + 4] };
#pragma unroll
                for (int mt = 0; mt < 2; mt++) {
                    int r = mt * 16 + (lane >> 2);
                    uint32_t af[4] = { hb[r * 68 + kq], hb[(r + 8) * 68 + kq],
                                       hb[r * 68 + kq + 4], hb[(r + 8) * 68 + kq + 4] };
                    mma8(acc[mt], af, bf);
                }
            }
            __syncthreads();
            if (c + 2 < 16) {
                issueH(c + 2);
                if (c + 2 >= KPC) issueW(c + 2);
                cp_commit();
            }
        }

        // dump gate fragments
        {
            int rowb = lane >> 2, colb = warp * 8 + 2 * (lane & 3);
#pragma unroll
            for (int mt = 0; mt < 2; mt++) {
                GS[(mt * 16 + rowb) * 64 + colb]         = acc[mt][0];
                GS[(mt * 16 + rowb) * 64 + colb + 1]     = acc[mt][1];
                GS[(mt * 16 + rowb + 8) * 64 + colb]     = acc[mt][2];
                GS[(mt * 16 + rowb + 8) * 64 + colb + 1] = acc[mt][3];
            }
        }
        __syncthreads();

        // LSTM cell elementwise
#pragma unroll
        for (int p2 = 0; p2 < 2; p2++) {
            int p = tid + p2 * 256, b = p >> 4, jl = p & 15;
            int len = SLEN[b];
            bool msk = (t < len);
            float gi = GS[b * 64 + jl]      + xr[p2][0];
            float gf = GS[b * 64 + 16 + jl] + xr[p2][1];
            float gg = GS[b * 64 + 32 + jl] + xr[p2][2];
            float go = GS[b * 64 + 48 + jl] + xr[p2][3];
            if (msk) {
                float ii = sigmoidf_(gi), ff = sigmoidf_(gf);
                float gv = tanhf(gg),     oo = sigmoidf_(go);
                float cn = ff * CST[p] + ii * gv;
                float hn = oo * tanhf(cn);
                CST[p] = cn; HST[p] = hn;
                hdir[b * H_ + j0 + jl] = f2tf(hn);
            }
            if (out) {
                int pout = dir ? ((t < len) ? (len - 1 - t) : t) : t;
                out[((size_t)(b * T_ + pout)) * (2 * H_) + dir * H_ + j0 + jl] = f2tf(HST[p]);
            }
        }
        grid_barrier();
    }
}

// ---------------- kernel 4: final linear  out = [h2b, h2f] @ lin_w^T + b ---
__global__ __launch_bounds__(256) void final_linear_kernel(
    const uint32_t* __restrict__ hF, const uint32_t* __restrict__ hB,
    const float* __restrict__ lw, const float* __restrict__ lb,
    float* __restrict__ outp)
{
    int w = (blockIdx.x * blockDim.x + threadIdx.x) >> 5;
    int lane = threadIdx.x & 31;
    if (w >= B_ * 2) return;
    int b = w >> 1, c = w & 1;
    float s = 0.f;
    for (int k = lane; k < 2 * H_; k += 32) {
        float xv = __uint_as_float((k < H_) ? hB[b * H_ + k] : hF[b * H_ + (k - H_)]);
        s += xv * lw[c * 2 * H_ + k];
    }
#pragma unroll
    for (int o = 16; o; o >>= 1) s += __shfl_xor_sync(0xffffffffu, s, o);
    if (lane == 0) outp[b * 2 + c] = s + lb[c];
}

// ---------------- launch ----------------------------------------------------
extern "C" void kernel_launch(void* const* d_in, const int* in_sizes, int n_in,
                              void* d_out, int out_size)
{
    const int*   tok      = (const int*)  d_in[0];
    const int*   lens     = (const int*)  d_in[1];
    const float* emb      = (const float*)d_in[2];
    const float* w_ih_l0f = (const float*)d_in[3];
    const float* w_hh_l0f = (const float*)d_in[4];
    const float* b_ih_l0f = (const float*)d_in[5];
    const float* b_hh_l0f = (const float*)d_in[6];
    const float* w_ih_l0b = (const float*)d_in[7];
    const float* w_hh_l0b = (const float*)d_in[8];
    const float* b_ih_l0b = (const float*)d_in[9];
    const float* b_hh_l0b = (const float*)d_in[10];
    const float* w_ih_l1f = (const float*)d_in[11];
    const float* w_hh_l1f = (const float*)d_in[12];
    const float* b_ih_l1f = (const float*)d_in[13];
    const float* b_hh_l1f = (const float*)d_in[14];
    const float* w_ih_l1b = (const float*)d_in[15];
    const float* w_hh_l1b = (const float*)d_in[16];
    const float* b_ih_l1b = (const float*)d_in[17];
    const float* b_hh_l1b = (const float*)d_in[18];
    const float* lin_w    = (const float*)d_in[19];
    const float* lin_b    = (const float*)d_in[20];

    uint32_t *x, *wA, *wB, *whF, *whB, *out0, *hF, *hB;
    float *xpF, *xpB;
    cudaGetSymbolAddress((void**)&x,    g_x);
    cudaGetSymbolAddress((void**)&wA,   g_wA);
    cudaGetSymbolAddress((void**)&wB,   g_wB);
    cudaGetSymbolAddress((void**)&whF,  g_whF);
    cudaGetSymbolAddress((void**)&whB,  g_whB);
    cudaGetSymbolAddress((void**)&xpF,  g_xpF);
    cudaGetSymbolAddress((void**)&xpB,  g_xpB);
    cudaGetSymbolAddress((void**)&out0, g_out0);
    cudaGetSymbolAddress((void**)&hF,   g_hF);
    cudaGetSymbolAddress((void**)&hB,   g_hB);

    cudaFuncSetAttribute(gemm_tf32, cudaFuncAttributeMaxDynamicSharedMemorySize, GEMM_SMEM);
    cudaFuncSetAttribute(lstm_layer_kernel, cudaFuncAttributeMaxDynamicSharedMemorySize, LSTM_SMEM);

    dim3 gg(G4_ / 128, M_ / 128);

    // 1. embedding gather -> tf32, K padded to 320
    gather_kernel<<<(M_ * EP_ + 255) / 256, 256>>>(tok, emb, x);

    // 2. convert layer-0 weights, then input projections (Ka = 320)
    conv_tf32<<<(G4_ * EP_ + 255) / 256, 256>>>(w_ih_l0f, wA, G4_, E_, EP_);
    conv_tf32<<<(G4_ * EP_ + 255) / 256, 256>>>(w_ih_l0b, wB, G4_, E_, EP_);
    conv_tf32<<<(G4_ * H_ + 255) / 256, 256>>>(w_hh_l0f, whF, G4_, H_, H_);
    conv_tf32<<<(G4_ * H_ + 255) / 256, 256>>>(w_hh_l0b, whB, G4_, H_, H_);
    gemm_tf32<<<gg, 256, GEMM_SMEM>>>(x, wA, b_ih_l0f, b_hh_l0f, xpF, EP_);
    gemm_tf32<<<gg, 256, GEMM_SMEM>>>(x, wB, b_ih_l0b, b_hh_l0b, xpB, EP_);

    // 3. layer-0 recurrence (writes [out_f || out_b] as tf32)
    lstm_layer_kernel<<<NCTA_REC, 256, LSTM_SMEM>>>(xpF, xpB, whF, whB, lens,
                                                    out0, hF, hB);

    // 4. convert layer-1 weights, then input projections (Ka = 2048)
    conv_tf32<<<(G4_ * 2048 + 255) / 256, 256>>>(w_ih_l1f, wA, G4_, 2 * H_, 2 * H_);
    conv_tf32<<<(G4_ * 2048 + 255) / 256, 256>>>(w_ih_l1b, wB, G4_, 2 * H_, 2 * H_);
    conv_tf32<<<(G4_ * H_ + 255) / 256, 256>>>(w_hh_l1f, whF, G4_, H_, H_);
    conv_tf32<<<(G4_ * H_ + 255) / 256, 256>>>(w_hh_l1b, whB, G4_, H_, H_);
    gemm_tf32<<<gg, 256, GEMM_SMEM>>>(out0, wA, b_ih_l1f, b_hh_l1f, xpF, 2 * H_);
    gemm_tf32<<<gg, 256, GEMM_SMEM>>>(out0, wB, b_ih_l1b, b_hh_l1b, xpB, 2 * H_);

    // 5. layer-1 recurrence (only final hiddens needed)
    lstm_layer_kernel<<<NCTA_REC, 256, LSTM_SMEM>>>(xpF, xpB, whF, whB, lens,
                                                    (uint32_t*)nullptr, hF, hB);

    // 6. head
    final_linear_kernel<<<8, 256>>>(hF, hB, lin_w, lin_b, (float*)d_out);
}